// round 14
// baseline (speedup 1.0000x reference)
#include <cuda_runtime.h>
#include <cstdint>

#define B 8
#define C 21
#define H 512
#define W 512
#define HW (H * W)          // 262144
#define NPIX (B * HW)       // 2097152
#define IGNORE_INDEX 255

#define BLOCK 256
#define ROWS_PB 4                         // rows per block
#define GRID (B * H / ROWS_PB)            // 1024 blocks
// smem: packed targets 6 rows x 8 batches x 128 u32 = 24KB; colany 4x128 u32 = 2KB

// Scratch (allocation-free rule: __device__ globals; zero-init at load,
// reset by the finalizer each run -> deterministic graph replays)
__device__ double   g_acc;
__device__ unsigned g_done;

__device__ __forceinline__ unsigned pack_u8(int4 v) {
    return (unsigned)(v.x & 0xFF) | ((unsigned)(v.y & 0xFF) << 8)
         | ((unsigned)(v.z & 0xFF) << 16) | ((unsigned)(v.w & 0xFF) << 24);
}

__global__ void __launch_bounds__(BLOCK, 4) fused_kernel(
    const float* __restrict__ in, const int* __restrict__ tgt,
    float* __restrict__ out)
{
    __shared__ unsigned s_t8[6 * 8 * 128];   // [row6][batch][wordquad] packed u8 targets
    __shared__ unsigned s_ca[4 * 128];       // [lr][wordquad] colany bytes (nonzero = differs)
    __shared__ float warp_sums[BLOCK / 32];

    int tid = threadIdx.x;
    int myb = blockIdx.x >> 7;               // batch of this block
    int i0  = (blockIdx.x & 127) * ROWS_PB;  // first pixel row of this block

    // ---- Prep 1: load 6 target rows (i0-1..i0+4, clamped) x 8 batches, pack u8 -> smem ----
    #pragma unroll 4
    for (int k = 0; k < 24; k++) {
        int idx = tid + k * 256;             // 0..6143
        int rb  = idx >> 7;                  // r6*8 + b
        int wq  = idx & 127;
        int r6  = rb >> 3;
        int b   = rb & 7;
        int gr  = min(max(i0 - 1 + r6, 0), H - 1);
        int4 v  = *reinterpret_cast<const int4*>(tgt + b * HW + gr * W + wq * 4);
        s_t8[idx] = pack_u8(v);
    }
    __syncthreads();

    // ---- Prep 2: colany rows lr=0..3 (global i0-1+lr): bytewise max!=min over 3 rows, OR over batch ----
    #pragma unroll
    for (int k = 0; k < 2; k++) {
        int idx = tid + k * 256;             // lr*128 + wq
        int lr  = idx >> 7;
        int wq  = idx & 127;
        unsigned acc = 0;
        #pragma unroll
        for (int b = 0; b < 8; b++) {
            unsigned a = s_t8[((lr    ) * 8 + b) * 128 + wq];
            unsigned m = s_t8[((lr + 1) * 8 + b) * 128 + wq];
            unsigned c = s_t8[((lr + 2) * 8 + b) * 128 + wq];
            unsigned mx = __vmaxu4(__vmaxu4(a, m), c);
            unsigned mn = __vminu4(__vminu4(a, m), c);
            acc |= (mx ^ mn);                // byte nonzero <=> max != min
        }
        s_ca[idx] = acc;
    }
    __syncthreads();

    const uint8_t* ca8 = reinterpret_cast<const uint8_t*>(s_ca);

    // ---- Stream: 2 quads/thread, fused CE (single-pass, no max-shift) + weight ----
    float contrib = 0.0f;
    #pragma unroll
    for (int k = 0; k < 2; k++) {
        int qidx = tid + k * 256;            // 0..511
        int plr  = qidx >> 7;                // local pixel row 0..3
        int j0   = (qidx & 127) << 2;
        int g    = i0 + plr;                 // global row
        int rem  = g * W + j0;

        const float* base = in + (size_t)myb * C * HW + rem;

        unsigned tw = s_t8[((plr + 1) * 8 + myb) * 128 + (j0 >> 2)];
        int tx = tw & 0xFF, ty = (tw >> 8) & 0xFF, tz = (tw >> 16) & 0xFF, tv = (tw >> 24) & 0xFF;

        // logits are O(1) -> exp safe without max-shift (rel_err budget 1e-3)
        float4 s  = make_float4(0.f, 0.f, 0.f, 0.f);
        float4 xt = make_float4(0.f, 0.f, 0.f, 0.f);
        #pragma unroll
        for (int c = 0; c < C; c++) {
            float4 x = *reinterpret_cast<const float4*>(base + (size_t)c * HW);
            s.x += __expf(x.x);  if (c == tx) xt.x = x.x;
            s.y += __expf(x.y);  if (c == ty) xt.y = x.y;
            s.z += __expf(x.z);  if (c == tz) xt.z = x.z;
            s.w += __expf(x.w);  if (c == tv) xt.w = x.w;
        }

        bool irow = (g >= 1) && (g <= H - 2);
        const uint8_t* car = ca8 + plr * 512;   // colany row (g-1), local

        #define DO_LANE(COMP, TT, LANE)                                         \
        {                                                                       \
            float ce = (TT == IGNORE_INDEX) ? 0.0f                              \
                                            : (__logf(s.COMP) - xt.COMP);       \
            int j = j0 + LANE;                                                  \
            float w = 1.0f;                                                     \
            if (irow && j >= 1 && j <= W - 2) {                                 \
                int any = car[j - 1] | car[j] | car[j + 1];                     \
                w = any ? 3.0f : 1.0f;                                          \
            }                                                                   \
            contrib += ce * w;                                                  \
        }
        DO_LANE(x, tx, 0)
        DO_LANE(y, ty, 1)
        DO_LANE(z, tz, 2)
        DO_LANE(w, tv, 3)
        #undef DO_LANE
    }

    // ---- Block reduction + last-block finalize ----
    int lane = tid & 31;
    int wid  = tid >> 5;
    #pragma unroll
    for (int off = 16; off > 0; off >>= 1)
        contrib += __shfl_down_sync(0xFFFFFFFF, contrib, off);
    if (lane == 0) warp_sums[wid] = contrib;
    __syncthreads();
    if (tid == 0) {
        float v = 0.0f;
        #pragma unroll
        for (int kk = 0; kk < BLOCK / 32; kk++) v += warp_sums[kk];
        atomicAdd(&g_acc, (double)v);
        __threadfence();
        unsigned done = atomicAdd(&g_done, 1u);
        if (done == GRID - 1) {
            out[0] = (float)(g_acc / (double)NPIX);
            // reset for next replay (all blocks' accumulates precede the last g_done)
            g_acc  = 0.0;
            g_done = 0u;
            __threadfence();
        }
    }
}

extern "C" void kernel_launch(void* const* d_in, const int* in_sizes, int n_in,
                              void* d_out, int out_size) {
    const float* inputs  = (const float*)d_in[0];
    const int*   targets = (const int*)d_in[1];
    float*       out     = (float*)d_out;

    fused_kernel<<<GRID, BLOCK>>>(inputs, targets, out);
}

// round 15
// speedup vs baseline: 1.1007x; 1.1007x over previous
#include <cuda_runtime.h>
#include <cstdint>

#define B 8
#define C 21
#define H 512
#define W 512
#define HW (H * W)          // 262144
#define NPIX (B * HW)       // 2097152
#define NOCT (NPIX / 8)     // 262144 (8 px per thread)
#define IGNORE_INDEX 255

#define MAIN_BLOCK 256
#define MAIN_GRID (NOCT / MAIN_BLOCK)   // 1024

// Scratch (allocation-free rule: __device__ globals)
__device__ uint8_t g_colany[H * W];
__device__ double   g_acc;
__device__ unsigned g_done;

// ---------------- Kernel 1: colany map + zero accumulators ----------------
__global__ void colany_kernel(const int* __restrict__ tgt) {
    int tid = blockIdx.x * blockDim.x + threadIdx.x;
    if (tid == 0) { g_acc = 0.0; g_done = 0u; }
    if (tid >= (H - 2) * (W / 4)) return;
    int i  = tid / (W / 4);
    int j0 = (tid % (W / 4)) * 4;

    uchar4 res = make_uchar4(0, 0, 0, 0);
    #pragma unroll
    for (int b = 0; b < B; b++) {
        const int* base = tgt + b * HW + i * W + j0;
        int4 r0 = *reinterpret_cast<const int4*>(base);
        int4 r1 = *reinterpret_cast<const int4*>(base + W);
        int4 r2 = *reinterpret_cast<const int4*>(base + 2 * W);
        res.x |= (max(max(r0.x, r1.x), r2.x) != min(min(r0.x, r1.x), r2.x));
        res.y |= (max(max(r0.y, r1.y), r2.y) != min(min(r0.y, r1.y), r2.y));
        res.z |= (max(max(r0.z, r1.z), r2.z) != min(min(r0.z, r1.z), r2.z));
        res.w |= (max(max(r0.w, r1.w), r2.w) != min(min(r0.w, r1.w), r2.w));
    }
    *reinterpret_cast<uchar4*>(&g_colany[i * W + j0]) = res;
}

// ---------------- Kernel 2: fused CE, 8 px/thread (2x float4, 1KB warp bursts) ----------------
__global__ void __launch_bounds__(MAIN_BLOCK, 3) main_kernel(
    const float* __restrict__ in, const int* __restrict__ tgt,
    float* __restrict__ out)
{
    int tid = blockIdx.x * MAIN_BLOCK + threadIdx.x;   // octet index, exact cover
    int p0  = tid << 3;
    int b   = p0 >> 18;          // / HW
    int rem = p0 & (HW - 1);
    int i   = rem >> 9;          // / W
    int j0  = rem & (W - 1);     // multiple of 8

    const float* base = in + (size_t)b * C * HW + rem;
    int4 tA = *reinterpret_cast<const int4*>(tgt + p0);
    int4 tB = *reinterpret_cast<const int4*>(tgt + p0 + 4);

    // single-pass softmax sums, no max-shift (N(0,1) logits; rel_err budget 1e-3)
    float4 sA  = make_float4(0.f, 0.f, 0.f, 0.f);
    float4 sB  = make_float4(0.f, 0.f, 0.f, 0.f);
    float4 xtA = make_float4(0.f, 0.f, 0.f, 0.f);
    float4 xtB = make_float4(0.f, 0.f, 0.f, 0.f);
    #pragma unroll
    for (int c = 0; c < C; c++) {
        const float* pc = base + (size_t)c * HW;
        float4 xa = *reinterpret_cast<const float4*>(pc);
        float4 xb = *reinterpret_cast<const float4*>(pc + 4);
        sA.x += __expf(xa.x);  if (c == tA.x) xtA.x = xa.x;
        sA.y += __expf(xa.y);  if (c == tA.y) xtA.y = xa.y;
        sA.z += __expf(xa.z);  if (c == tA.z) xtA.z = xa.z;
        sA.w += __expf(xa.w);  if (c == tA.w) xtA.w = xa.w;
        sB.x += __expf(xb.x);  if (c == tB.x) xtB.x = xb.x;
        sB.y += __expf(xb.y);  if (c == tB.y) xtB.y = xb.y;
        sB.z += __expf(xb.z);  if (c == tB.z) xtB.z = xb.z;
        sB.w += __expf(xb.w);  if (c == tB.w) xtB.w = xb.w;
    }

    bool irow = (i >= 1) && (i <= H - 2);
    const uint8_t* ca = &g_colany[(i - 1) * W];

    float contrib = 0.0f;
    #define DO_LANE(SV, XTV, TT, LANE)                                          \
    {                                                                           \
        float ce = (TT == IGNORE_INDEX) ? 0.0f : (__logf(SV) - XTV);            \
        int j = j0 + LANE;                                                      \
        float w = 1.0f;                                                         \
        if (irow && j >= 1 && j <= W - 2) {                                     \
            int any = ca[j - 1] | ca[j] | ca[j + 1];                            \
            w = any ? 3.0f : 1.0f;                                              \
        }                                                                       \
        contrib += ce * w;                                                      \
    }
    DO_LANE(sA.x, xtA.x, tA.x, 0)
    DO_LANE(sA.y, xtA.y, tA.y, 1)
    DO_LANE(sA.z, xtA.z, tA.z, 2)
    DO_LANE(sA.w, xtA.w, tA.w, 3)
    DO_LANE(sB.x, xtB.x, tB.x, 4)
    DO_LANE(sB.y, xtB.y, tB.y, 5)
    DO_LANE(sB.z, xtB.z, tB.z, 6)
    DO_LANE(sB.w, xtB.w, tB.w, 7)
    #undef DO_LANE

    // block reduction + last-block finalize
    __shared__ float warp_sums[MAIN_BLOCK / 32];
    int lane = threadIdx.x & 31;
    int wid  = threadIdx.x >> 5;
    #pragma unroll
    for (int off = 16; off > 0; off >>= 1)
        contrib += __shfl_down_sync(0xFFFFFFFF, contrib, off);
    if (lane == 0) warp_sums[wid] = contrib;
    __syncthreads();
    if (threadIdx.x == 0) {
        float v = 0.0f;
        #pragma unroll
        for (int k = 0; k < MAIN_BLOCK / 32; k++) v += warp_sums[k];
        atomicAdd(&g_acc, (double)v);
        __threadfence();
        unsigned done = atomicAdd(&g_done, 1u);
        if (done == MAIN_GRID - 1) {
            out[0] = (float)(g_acc / (double)NPIX);
        }
    }
}

extern "C" void kernel_launch(void* const* d_in, const int* in_sizes, int n_in,
                              void* d_out, int out_size) {
    const float* inputs  = (const float*)d_in[0];
    const int*   targets = (const int*)d_in[1];
    float*       out     = (float*)d_out;

    {
        int nthreads = (H - 2) * (W / 4);
        colany_kernel<<<(nthreads + 255) / 256, 256>>>(targets);
    }
    main_kernel<<<MAIN_GRID, MAIN_BLOCK>>>(inputs, targets, out);
}

// round 16
// speedup vs baseline: 1.1796x; 1.0717x over previous
#include <cuda_runtime.h>
#include <cstdint>

#define B 8
#define C 21
#define H 512
#define W 512
#define HW (H * W)          // 262144
#define NPIX (B * HW)       // 2097152
#define NQUAD (NPIX / 4)    // 524288
#define IGNORE_INDEX 255

#define GRID 592            // 4 blocks/SM x 148 SMs, co-resident (64 regs x 256 thr x 4 = full RF)
#define BLOCK 256
#define NTHREADS (GRID * BLOCK)

// Scratch (allocation-free rule: __device__ globals; zero-init at load,
// reset by the finalizer each run -> deterministic graph replays)
__device__ uint8_t g_colany[H * W];
__device__ double   g_acc;
__device__ unsigned g_bar;
__device__ unsigned g_done;

__global__ void __launch_bounds__(BLOCK, 4) fused_kernel(
    const float* __restrict__ in, const int* __restrict__ tgt,
    float* __restrict__ out)
{
    // ---------------- Phase 1: colany map (vertical-3 diff, OR over batch) ----------------
    for (int t = blockIdx.x * BLOCK + threadIdx.x; t < (H - 2) * (W / 4); t += NTHREADS) {
        int i  = t / (W / 4);
        int j0 = (t % (W / 4)) * 4;
        uchar4 res = make_uchar4(0, 0, 0, 0);
        #pragma unroll
        for (int b = 0; b < B; b++) {
            const int* base = tgt + b * HW + i * W + j0;
            int4 r0 = *reinterpret_cast<const int4*>(base);
            int4 r1 = *reinterpret_cast<const int4*>(base + W);
            int4 r2 = *reinterpret_cast<const int4*>(base + 2 * W);
            res.x |= (max(max(r0.x, r1.x), r2.x) != min(min(r0.x, r1.x), r2.x));
            res.y |= (max(max(r0.y, r1.y), r2.y) != min(min(r0.y, r1.y), r2.y));
            res.z |= (max(max(r0.z, r1.z), r2.z) != min(min(r0.z, r1.z), r2.z));
            res.w |= (max(max(r0.w, r1.w), r2.w) != min(min(r0.w, r1.w), r2.w));
        }
        *reinterpret_cast<uchar4*>(&g_colany[i * W + j0]) = res;
    }

    // ---------------- Software grid barrier (all GRID blocks co-resident) ----------------
    __syncthreads();
    if (threadIdx.x == 0) {
        __threadfence();                    // publish colany writes
        atomicAdd(&g_bar, 1u);
        while (atomicAdd(&g_bar, 0u) < GRID) { __nanosleep(64); }
    }
    __syncthreads();
    __threadfence();                        // acquire colany writes

    // ---------------- Phase 2: fused CE (float4, single-pass) + weight + reduce ----------------
    // Contiguous static partition: per-SM work balanced to +-1 quad
    int q_begin = (int)(((long long)blockIdx.x * NQUAD) / GRID);
    int q_end   = (int)(((long long)(blockIdx.x + 1) * NQUAD) / GRID);

    float contrib = 0.0f;
    for (int q = q_begin + threadIdx.x; q < q_end; q += BLOCK) {
        int p0  = q << 2;
        int b   = p0 >> 18;          // / HW
        int rem = p0 & (HW - 1);
        int i   = rem >> 9;          // / W
        int j0  = rem & (W - 1);     // multiple of 4

        const float* base = in + (size_t)b * C * HW + rem;
        int4 t4 = *reinterpret_cast<const int4*>(tgt + p0);

        // logits are O(1) -> exp safe without max-shift (rel_err budget 1e-3)
        float4 s  = make_float4(0.f, 0.f, 0.f, 0.f);
        float4 xt = make_float4(0.f, 0.f, 0.f, 0.f);
        #pragma unroll
        for (int c = 0; c < C; c++) {
            float4 x = *reinterpret_cast<const float4*>(base + (size_t)c * HW);
            s.x += __expf(x.x);  if (c == t4.x) xt.x = x.x;
            s.y += __expf(x.y);  if (c == t4.y) xt.y = x.y;
            s.z += __expf(x.z);  if (c == t4.z) xt.z = x.z;
            s.w += __expf(x.w);  if (c == t4.w) xt.w = x.w;
        }

        bool irow = (i >= 1) && (i <= H - 2);
        const uint8_t* ca = &g_colany[(i - 1) * W];

        #define DO_LANE(COMP, LANE)                                             \
        {                                                                       \
            float ce = (t4.COMP == IGNORE_INDEX) ? 0.0f                         \
                                                 : (__logf(s.COMP) - xt.COMP);  \
            int j = j0 + LANE;                                                  \
            float w = 1.0f;                                                     \
            if (irow && j >= 1 && j <= W - 2) {                                 \
                int any = ca[j - 1] | ca[j] | ca[j + 1];                        \
                w = any ? 3.0f : 1.0f;                                          \
            }                                                                   \
            contrib += ce * w;                                                  \
        }
        DO_LANE(x, 0)
        DO_LANE(y, 1)
        DO_LANE(z, 2)
        DO_LANE(w, 3)
        #undef DO_LANE
    }

    // ---------------- Block reduction + last-block finalize ----------------
    __shared__ float warp_sums[BLOCK / 32];
    int lane = threadIdx.x & 31;
    int wid  = threadIdx.x >> 5;
    #pragma unroll
    for (int off = 16; off > 0; off >>= 1)
        contrib += __shfl_down_sync(0xFFFFFFFF, contrib, off);
    if (lane == 0) warp_sums[wid] = contrib;
    __syncthreads();
    if (threadIdx.x == 0) {
        float v = 0.0f;
        #pragma unroll
        for (int k = 0; k < BLOCK / 32; k++) v += warp_sums[k];
        atomicAdd(&g_acc, (double)v);
        __threadfence();
        unsigned done = atomicAdd(&g_done, 1u);
        if (done == GRID - 1) {
            out[0] = (float)(g_acc / (double)NPIX);
            // reset for next replay: all blocks are past the barrier and the
            // accumulate by the time the last g_done arrives
            g_acc  = 0.0;
            g_bar  = 0u;
            g_done = 0u;
            __threadfence();
        }
    }
}

extern "C" void kernel_launch(void* const* d_in, const int* in_sizes, int n_in,
                              void* d_out, int out_size) {
    const float* inputs  = (const float*)d_in[0];
    const int*   targets = (const int*)d_in[1];
    float*       out     = (float*)d_out;

    fused_kernel<<<GRID, BLOCK>>>(inputs, targets, out);
}